// round 8
// baseline (speedup 1.0000x reference)
#include <cuda_runtime.h>

// RuleGraphConvLayer — GB300 sm_103a, round 8
//
// Reformulation: Y = feat @ Wn81 (pre-projection). Then
//   out[n] = Ps[n] + sum_e s_e*Y[dst_e] + c_n*(Y[n] - f0*Wn0 - f1*Wn1 - f2*Wn2)
//            + bagg[n] @ Wb
// where Ps = feat@w_s, c_n = sum s_e, bagg = sum bond_e, Wb = w_n rows 81..102.
// The aggregation now gathers 256B-aligned 64-float Y rows (2 L2 lines/edge)
// instead of 324B unaligned feat rows, and s_e is precomputed in scatter.

#define NF 81
#define FP 84      // padded feat pitch (336 B, 16B-aligned, 21 float4)
#define NB 22
#define OC 64
#define ZP 88      // z row pitch: [aggY 64 | bagg 22 | c @86 | pad]

#define MAX_NODES 100000
#define MAX_EDGES 800000

#define SCAN_T 1024
#define SCAN_E 4
#define SCAN_B (SCAN_T * SCAN_E)

__device__ __align__(16) float g_featp[MAX_NODES * FP];
__device__ __align__(16) float g_Y[MAX_NODES * OC];
__device__ __align__(16) float g_Ps[MAX_NODES * OC];
__device__ __align__(16) float g_z[MAX_NODES * ZP];
__device__ __align__(16) int4  g_sorted[MAX_EDGES];
__device__ int g_hist[MAX_NODES];          // zero at load; scan1 re-zeroes
__device__ int g_start[MAX_NODES + 1];
__device__ int g_cursor[MAX_NODES];
__device__ int g_bsum[64];

// ---------------------------------------------------------------------------
// K1: repack feat -> g_featp (pitch 84, zero-padded) fused with src histogram.
// First `rblocks` blocks repack; the rest histogram.
// ---------------------------------------------------------------------------
__global__ void repack_hist_kernel(const float* __restrict__ feat,
                                   const int* __restrict__ src,
                                   int n_nodes, int n_edges, int rblocks) {
    int b = blockIdx.x;
    int t = threadIdx.x;
    if (b < rblocks) {
        int j = b * 256 + t;                    // float4 index into g_featp
        int total = n_nodes * (FP / 4);         // 21 float4 per row
        if (j < total) {
            int n = j / (FP / 4);
            int q = j - n * (FP / 4);
            int k = q * 4;
            const float* fr = feat + (size_t)n * NF;
            float4 v;
            v.x = (k + 0 < NF) ? __ldg(fr + k + 0) : 0.f;
            v.y = (k + 1 < NF) ? __ldg(fr + k + 1) : 0.f;
            v.z = (k + 2 < NF) ? __ldg(fr + k + 2) : 0.f;
            v.w = (k + 3 < NF) ? __ldg(fr + k + 3) : 0.f;
            reinterpret_cast<float4*>(g_featp)[j] = v;
        }
    } else {
        int e = (b - rblocks) * 256 + t;
        if (e < n_edges) atomicAdd(&g_hist[src[e]], 1);
    }
}

// ---------------------------------------------------------------------------
// K2: per-block exclusive scan (4096/block); totals to g_bsum; self-zeroes hist
// ---------------------------------------------------------------------------
__global__ __launch_bounds__(SCAN_T) void scan1_kernel(int n) {
    __shared__ int wsum[32];
    int t = threadIdx.x;
    int base = blockIdx.x * SCAN_B + t * SCAN_E;
    int v[SCAN_E];
    int local = 0;
    #pragma unroll
    for (int j = 0; j < SCAN_E; j++) {
        int i = base + j;
        v[j] = (i < n) ? g_hist[i] : 0;
        if (i < n) g_hist[i] = 0;
        local += v[j];
    }
    int lane = t & 31, w = t >> 5;
    int inc = local;
    #pragma unroll
    for (int d = 1; d < 32; d <<= 1) {
        int x = __shfl_up_sync(0xFFFFFFFF, inc, d);
        if (lane >= d) inc += x;
    }
    if (lane == 31) wsum[w] = inc;
    __syncthreads();
    if (t < 32) {
        int x = wsum[t];
        #pragma unroll
        for (int d = 1; d < 32; d <<= 1) {
            int y = __shfl_up_sync(0xFFFFFFFF, x, d);
            if (t >= d) x += y;
        }
        wsum[t] = x;
    }
    __syncthreads();
    int run = inc - local + ((w > 0) ? wsum[w - 1] : 0);
    #pragma unroll
    for (int j = 0; j < SCAN_E; j++) {
        if (base + j < n) g_start[base + j] = run;
        run += v[j];
    }
    if (t == SCAN_T - 1) g_bsum[blockIdx.x] = run;
}

// ---------------------------------------------------------------------------
// K3: scan block sums (redundant per block) + apply offsets + init cursors
// ---------------------------------------------------------------------------
__global__ __launch_bounds__(256) void scan23_kernel(int n, int n_edges, int nsb) {
    __shared__ int off[32];
    int t = threadIdx.x;
    if (t < 32) {
        int x = (t < nsb) ? g_bsum[t] : 0;
        int inc = x;
        #pragma unroll
        for (int d = 1; d < 32; d <<= 1) {
            int y = __shfl_up_sync(0xFFFFFFFF, inc, d);
            if (t >= d) inc += y;
        }
        off[t] = inc - x;
    }
    __syncthreads();
    int i = blockIdx.x * 256 + t;
    if (i < n) {
        int v = g_start[i] + off[i / SCAN_B];
        g_start[i] = v;
        g_cursor[i] = v;
    }
    if (i == 0) g_start[n] = n_edges;
}

// ---------------------------------------------------------------------------
// K4: scatter — computes s_e and writes (dst, eid, s) into per-src slots
// ---------------------------------------------------------------------------
__global__ void scatter_kernel(const int* __restrict__ src,
                               const int* __restrict__ dst,
                               int n_edges) {
    int e = blockIdx.x * blockDim.x + threadIdx.x;
    if (e >= n_edges) return;
    int s = src[e];
    int d = dst[e];
    float4 cs = __ldg(reinterpret_cast<const float4*>(g_featp + (size_t)s * FP));
    float4 cd = __ldg(reinterpret_cast<const float4*>(g_featp + (size_t)d * FP));
    float dx = cs.x - cd.x, dy = cs.y - cd.y, dz = cs.z - cd.z;
    float dd = dx * dx + dy * dy + dz * dz;
    float sc = (dd > 0.f) ? __frcp_rn(dd) : 10000.f;
    int pos = atomicAdd(&g_cursor[s], 1);
    g_sorted[pos] = make_int4(d, e, __float_as_int(sc), 0);
}

// ---------------------------------------------------------------------------
// K5: proj — [Ps | Y] = featp @ [w_s | Wn81].  K=84 (3 zero rows), N=128.
// Block: 256 threads; warps 0-3 -> Ps half (nodes blockIdx*128+0..127),
// warps 4-7 -> Y half (same nodes). One node per thread, 32 f32x2 accs.
// ---------------------------------------------------------------------------
__device__ __forceinline__ void fma2_step(unsigned long long* acc,
                                          const float* wrow, float xv) {
    unsigned long long xx;
    asm("mov.b64 %0, {%1, %1};" : "=l"(xx) : "f"(xv));
    const ulonglong2* w2 = reinterpret_cast<const ulonglong2*>(wrow);
    #pragma unroll
    for (int j = 0; j < 16; j++) {
        ulonglong2 wv = w2[j];
        asm("fma.rn.f32x2 %0, %1, %2, %0;" : "+l"(acc[2 * j + 0]) : "l"(xx), "l"(wv.x));
        asm("fma.rn.f32x2 %0, %1, %2, %0;" : "+l"(acc[2 * j + 1]) : "l"(xx), "l"(wv.y));
    }
}

__global__ __launch_bounds__(256) void proj_kernel(
    const float* __restrict__ w_s,   // [81][64]
    const float* __restrict__ w_n,   // [103][64]
    int n_nodes) {

    __shared__ __align__(16) float Wsh[FP * 128];   // 84 x 128 = 43008 B

    int t = threadIdx.x;
    #pragma unroll
    for (int r = 0; r < 42; r++) {                  // 42*256 == 84*128
        int idx = r * 256 + t;
        int k = idx >> 7;
        int c = idx & 127;
        float v = 0.f;
        if (k < NF) v = (c < OC) ? __ldg(w_s + k * OC + c)
                                 : __ldg(w_n + k * OC + (c - OC));
        Wsh[idx] = v;
    }
    __syncthreads();

    int half = t >> 7;                  // 0 -> Ps, 1 -> Y
    int node = blockIdx.x * 128 + (t & 127);
    if (node >= n_nodes) return;

    const float4* xrow = reinterpret_cast<const float4*>(g_featp + (size_t)node * FP);
    const float* wbase = Wsh + half * OC;

    unsigned long long acc[32];
    #pragma unroll
    for (int j = 0; j < 32; j++) acc[j] = 0ull;

    float4 xv = __ldg(xrow);
    #pragma unroll 3
    for (int i = 0; i < 21; i++) {
        float4 cur = xv;
        if (i + 1 < 21) xv = __ldg(xrow + i + 1);
        fma2_step(acc, wbase + (i * 4 + 0) * 128, cur.x);
        fma2_step(acc, wbase + (i * 4 + 1) * 128, cur.y);
        fma2_step(acc, wbase + (i * 4 + 2) * 128, cur.z);
        fma2_step(acc, wbase + (i * 4 + 3) * 128, cur.w);
    }

    float* orow = (half ? g_Y : g_Ps) + (size_t)node * OC;
    #pragma unroll
    for (int j = 0; j < 16; j++) {
        float x0, x1, x2, x3;
        asm("mov.b64 {%0, %1}, %2;" : "=f"(x0), "=f"(x1) : "l"(acc[2 * j + 0]));
        asm("mov.b64 {%0, %1}, %2;" : "=f"(x2), "=f"(x3) : "l"(acc[2 * j + 1]));
        reinterpret_cast<float4*>(orow)[j] = make_float4(x0, x1, x2, x3);
    }
}

// ---------------------------------------------------------------------------
// K6: agg — warp per node. Per edge: 1 broadcast int4 + 2 single-line Y loads
// + 1 bond load + 4 FFMA. 4-edge pipeline. Writes z row.
// ---------------------------------------------------------------------------
__global__ __launch_bounds__(256) void agg_kernel(
    const float* __restrict__ bond,
    int n_nodes) {

    int n = (int)((blockIdx.x * 256 + threadIdx.x) >> 5);
    int lane = threadIdx.x & 31;
    if (n >= n_nodes) return;

    int beg = __ldg(g_start + n);
    int end = __ldg(g_start + n + 1);
    bool hasb = (lane < NB);

    float ay0 = 0.f, ay1 = 0.f, ab = 0.f, ac = 0.f;

    int i = beg;
    for (; i + 3 < end; i += 4) {
        float y0[4], y1[4], bv[4], s[4];
        #pragma unroll
        for (int j = 0; j < 4; j++) {
            int4 r = __ldg(g_sorted + i + j);
            const float* yr = g_Y + (size_t)r.x * OC;
            y0[j] = __ldg(yr + lane);
            y1[j] = __ldg(yr + lane + 32);
            bv[j] = hasb ? __ldg(bond + (size_t)r.y * NB + lane) : 0.f;
            s[j] = __int_as_float(r.z);
        }
        #pragma unroll
        for (int j = 0; j < 4; j++) {
            ay0 += s[j] * y0[j];
            ay1 += s[j] * y1[j];
            ab += bv[j];
            ac += s[j];
        }
    }
    for (; i < end; i++) {
        int4 r = __ldg(g_sorted + i);
        const float* yr = g_Y + (size_t)r.x * OC;
        float y0 = __ldg(yr + lane);
        float y1 = __ldg(yr + lane + 32);
        float bv = hasb ? __ldg(bond + (size_t)r.y * NB + lane) : 0.f;
        float s = __int_as_float(r.z);
        ay0 += s * y0;
        ay1 += s * y1;
        ab += bv;
        ac += s;
    }

    float* zr = g_z + (size_t)n * ZP;
    zr[lane] = ay0;
    zr[lane + 32] = ay1;
    if (hasb) zr[OC + lane] = ab;
    if (lane == 31) zr[86] = ac;        // ac is warp-uniform
}

// ---------------------------------------------------------------------------
// K7: combine — out = Ps + aggY + c*Y - c*(f0*Wn0+f1*Wn1+f2*Wn2) + bagg@Wb
// One node per thread; Wb (22 rows) + Wn[0:3] staged in smem.
// ---------------------------------------------------------------------------
__global__ __launch_bounds__(256) void combine_kernel(
    const float* __restrict__ w_n,   // [103][64]
    float* __restrict__ out,
    int n_nodes) {

    __shared__ __align__(16) float Wc[25 * OC];   // rows 0..21 = Wb, 22..24 = Wn[0..2]

    int t = threadIdx.x;
    for (int idx = t; idx < 25 * OC; idx += 256) {
        int k = idx >> 6;
        int c = idx & (OC - 1);
        Wc[idx] = (k < NB) ? __ldg(w_n + (NF + k) * OC + c)
                           : __ldg(w_n + (k - NB) * OC + c);
    }
    __syncthreads();

    int node = blockIdx.x * 256 + t;
    if (node >= n_nodes) return;

    const float4* z4 = reinterpret_cast<const float4*>(g_z + (size_t)node * ZP);
    const float4* ps4 = reinterpret_cast<const float4*>(g_Ps + (size_t)node * OC);
    const float4* y4 = reinterpret_cast<const float4*>(g_Y + (size_t)node * OC);
    float4 fh = __ldg(reinterpret_cast<const float4*>(g_featp + (size_t)node * FP));

    float4 ztail = __ldg(z4 + 21);       // floats 84..87; .z = c_n
    float cn = ztail.z;

    unsigned long long acc[32];
    #pragma unroll
    for (int j = 0; j < 16; j++) {
        float4 ps = __ldg(ps4 + j);
        float4 yy = __ldg(y4 + j);
        float4 ay = __ldg(z4 + j);
        float a0 = ps.x + ay.x + cn * yy.x;
        float a1 = ps.y + ay.y + cn * yy.y;
        float a2 = ps.z + ay.z + cn * yy.z;
        float a3 = ps.w + ay.w + cn * yy.w;
        asm("mov.b64 %0, {%1, %2};" : "=l"(acc[2 * j + 0]) : "f"(a0), "f"(a1));
        asm("mov.b64 %0, {%1, %2};" : "=l"(acc[2 * j + 1]) : "f"(a2), "f"(a3));
    }

    // rank-3 correction: acc -= cn*f_k * Wn[k]
    fma2_step(acc, Wc + 22 * OC, -cn * fh.x);
    fma2_step(acc, Wc + 23 * OC, -cn * fh.y);
    fma2_step(acc, Wc + 24 * OC, -cn * fh.z);

    // bagg @ Wb: bagg = z floats 64..85
    float bg[24];
    #pragma unroll
    for (int j = 0; j < 6; j++) {
        float4 v = __ldg(z4 + 16 + j);
        bg[4 * j + 0] = v.x; bg[4 * j + 1] = v.y;
        bg[4 * j + 2] = v.z; bg[4 * j + 3] = v.w;
    }
    #pragma unroll
    for (int k = 0; k < NB; k++)
        fma2_step(acc, Wc + k * OC, bg[k]);

    float* orow = out + (size_t)node * OC;
    #pragma unroll
    for (int j = 0; j < 16; j++) {
        float x0, x1, x2, x3;
        asm("mov.b64 {%0, %1}, %2;" : "=f"(x0), "=f"(x1) : "l"(acc[2 * j + 0]));
        asm("mov.b64 {%0, %1}, %2;" : "=f"(x2), "=f"(x3) : "l"(acc[2 * j + 1]));
        reinterpret_cast<float4*>(orow)[j] = make_float4(x0, x1, x2, x3);
    }
}

// ---------------------------------------------------------------------------
extern "C" void kernel_launch(void* const* d_in, const int* in_sizes, int n_in,
                              void* d_out, int out_size) {
    const float* feat = (const float*)d_in[0];
    const float* bond = (const float*)d_in[1];
    const float* w_s  = (const float*)d_in[2];
    const float* w_n  = (const float*)d_in[3];
    const int*   src  = (const int*)d_in[4];
    const int*   dst  = (const int*)d_in[5];
    float* out = (float*)d_out;

    int n_nodes = in_sizes[0] / NF;
    int n_edges = in_sizes[4];
    int nsb = (n_nodes + SCAN_B - 1) / SCAN_B;

    int rblocks = (n_nodes * (FP / 4) + 255) / 256;
    int hblocks = (n_edges + 255) / 256;

    repack_hist_kernel<<<rblocks + hblocks, 256>>>(feat, src, n_nodes, n_edges, rblocks);
    scan1_kernel<<<nsb, SCAN_T>>>(n_nodes);
    scan23_kernel<<<(n_nodes + 255) / 256, 256>>>(n_nodes, n_edges, nsb);
    scatter_kernel<<<(n_edges + 255) / 256, 256>>>(src, dst, n_edges);
    proj_kernel<<<(n_nodes + 127) / 128, 256>>>(w_s, w_n, n_nodes);
    agg_kernel<<<(n_nodes * 32 + 255) / 256, 256>>>(bond, n_nodes);
    combine_kernel<<<(n_nodes + 255) / 256, 256>>>(w_n, out, n_nodes);
}

// round 9
// speedup vs baseline: 1.1533x; 1.1533x over previous
#include <cuda_runtime.h>

// RuleGraphConvLayer — GB300 sm_103a, round 9
//
// Y = feat @ Wn81 pre-projection:
//   out[n] = Ps[n] + sum_e s_e*Y[dst_e] + c_n*(Y[n] - f0*Wn0 - f1*Wn1 - f2*Wn2)
//            + bagg[n] @ Wb
//
// R9: 4 launches (fixed per-launch cost ~12-15us measured):
//   K1 repack+hist | K2 scan1 (block-local) | K3 scatter∪proj | K4 agg+combine
// Block offsets for the scan are recomputed per-block from g_bsum (25-elem
// warp scan in smem) instead of a dedicated scan23 launch. g_hist doubles as
// the scatter cursor (zeroed by scan1, re-zeroed by K4 for graph replay).

#define NF 81
#define FP 84      // padded feat pitch (336 B, 21 float4)
#define NB 22
#define OC 64

#define MAX_NODES 100000
#define MAX_EDGES 800000

#define SCAN_T 1024
#define SCAN_E 4
#define SCAN_B (SCAN_T * SCAN_E)   // 4096

__device__ __align__(16) float g_featp[MAX_NODES * FP];
__device__ __align__(16) float g_Y[MAX_NODES * OC];
__device__ __align__(16) float g_Ps[MAX_NODES * OC];
__device__ __align__(16) int4  g_sorted[MAX_EDGES];
__device__ int g_hist[MAX_NODES];      // zero at load; scan1 zeroes; K4 re-zeroes
__device__ int g_start[MAX_NODES];     // block-LOCAL exclusive prefix
__device__ int g_bsum[64];

// ---------------------------------------------------------------------------
// K1: repack feat -> g_featp (pitch 84, zero-padded) fused with src histogram
// ---------------------------------------------------------------------------
__global__ void repack_hist_kernel(const float* __restrict__ feat,
                                   const int* __restrict__ src,
                                   int n_nodes, int n_edges, int rblocks) {
    int b = blockIdx.x;
    int t = threadIdx.x;
    if (b < rblocks) {
        int j = b * 256 + t;
        int total = n_nodes * (FP / 4);
        if (j < total) {
            int n = j / (FP / 4);
            int q = j - n * (FP / 4);
            int k = q * 4;
            const float* fr = feat + (size_t)n * NF;
            float4 v;
            v.x = (k + 0 < NF) ? __ldg(fr + k + 0) : 0.f;
            v.y = (k + 1 < NF) ? __ldg(fr + k + 1) : 0.f;
            v.z = (k + 2 < NF) ? __ldg(fr + k + 2) : 0.f;
            v.w = (k + 3 < NF) ? __ldg(fr + k + 3) : 0.f;
            reinterpret_cast<float4*>(g_featp)[j] = v;
        }
    } else {
        int e = (b - rblocks) * 256 + t;
        if (e < n_edges) atomicAdd(&g_hist[src[e]], 1);
    }
}

// ---------------------------------------------------------------------------
// K2: per-block exclusive scan (block-local); totals to g_bsum; zeroes g_hist
// ---------------------------------------------------------------------------
__global__ __launch_bounds__(SCAN_T) void scan1_kernel(int n) {
    __shared__ int wsum[32];
    int t = threadIdx.x;
    int base = blockIdx.x * SCAN_B + t * SCAN_E;
    int v[SCAN_E];
    int local = 0;
    #pragma unroll
    for (int j = 0; j < SCAN_E; j++) {
        int i = base + j;
        v[j] = (i < n) ? g_hist[i] : 0;
        if (i < n) g_hist[i] = 0;          // becomes the scatter cursor
        local += v[j];
    }
    int lane = t & 31, w = t >> 5;
    int inc = local;
    #pragma unroll
    for (int d = 1; d < 32; d <<= 1) {
        int x = __shfl_up_sync(0xFFFFFFFF, inc, d);
        if (lane >= d) inc += x;
    }
    if (lane == 31) wsum[w] = inc;
    __syncthreads();
    if (t < 32) {
        int x = wsum[t];
        #pragma unroll
        for (int d = 1; d < 32; d <<= 1) {
            int y = __shfl_up_sync(0xFFFFFFFF, x, d);
            if (t >= d) x += y;
        }
        wsum[t] = x;
    }
    __syncthreads();
    int run = inc - local + ((w > 0) ? wsum[w - 1] : 0);   // block-local exclusive
    #pragma unroll
    for (int j = 0; j < SCAN_E; j++) {
        if (base + j < n) g_start[base + j] = run;
        run += v[j];
    }
    if (t == SCAN_T - 1) g_bsum[blockIdx.x] = run;
}

// warp-scan of g_bsum into smem offsets (call with t = threadIdx.x, t<32 active)
__device__ __forceinline__ void load_block_offsets(int* off, int t, int nsb) {
    if (t < 32) {
        int x = (t < nsb) ? g_bsum[t] : 0;
        int inc = x;
        #pragma unroll
        for (int d = 1; d < 32; d <<= 1) {
            int y = __shfl_up_sync(0xFFFFFFFF, inc, d);
            if (t >= d) inc += y;
        }
        off[t] = inc - x;   // exclusive
    }
}

// ---------------------------------------------------------------------------
// FFMA2 helper (broadcast W row from smem)
// ---------------------------------------------------------------------------
__device__ __forceinline__ void fma2_step(unsigned long long* acc,
                                          const float* wrow, float xv) {
    unsigned long long xx;
    asm("mov.b64 %0, {%1, %1};" : "=l"(xx) : "f"(xv));
    const ulonglong2* w2 = reinterpret_cast<const ulonglong2*>(wrow);
    #pragma unroll
    for (int j = 0; j < 16; j++) {
        ulonglong2 wv = w2[j];
        asm("fma.rn.f32x2 %0, %1, %2, %0;" : "+l"(acc[2 * j + 0]) : "l"(xx), "l"(wv.x));
        asm("fma.rn.f32x2 %0, %1, %2, %0;" : "+l"(acc[2 * j + 1]) : "l"(xx), "l"(wv.y));
    }
}

// ---------------------------------------------------------------------------
// K3: scatter ∪ proj (heterogeneous blocks, no inter-dependency).
//   proj blocks  (< pblocks): [Ps|Y] = featp @ [w_s|Wn81], K=84, N=128
//   scatter blocks: s_e + slot via g_start_local + off + atomic g_hist
// ---------------------------------------------------------------------------
__global__ __launch_bounds__(256) void scatter_proj_kernel(
    const float* __restrict__ w_s,
    const float* __restrict__ w_n,
    const int* __restrict__ src,
    const int* __restrict__ dst,
    int n_nodes, int n_edges, int pblocks, int nsb) {

    __shared__ __align__(16) float Wsh[FP * 128];   // 43008 B
    __shared__ int off[32];

    int t = threadIdx.x;

    if ((int)blockIdx.x < pblocks) {
        // ---- proj ----
        #pragma unroll
        for (int r = 0; r < 42; r++) {              // 42*256 == 84*128
            int idx = r * 256 + t;
            int k = idx >> 7;
            int c = idx & 127;
            float v = 0.f;
            if (k < NF) v = (c < OC) ? __ldg(w_s + k * OC + c)
                                     : __ldg(w_n + k * OC + (c - OC));
            Wsh[idx] = v;
        }
        __syncthreads();

        int half = t >> 7;
        int node = blockIdx.x * 128 + (t & 127);
        if (node >= n_nodes) return;

        const float4* xrow = reinterpret_cast<const float4*>(g_featp + (size_t)node * FP);
        const float* wbase = Wsh + half * OC;

        unsigned long long acc[32];
        #pragma unroll
        for (int j = 0; j < 32; j++) acc[j] = 0ull;

        float4 xv = __ldg(xrow);
        #pragma unroll 3
        for (int i = 0; i < 21; i++) {
            float4 cur = xv;
            if (i + 1 < 21) xv = __ldg(xrow + i + 1);
            fma2_step(acc, wbase + (i * 4 + 0) * 128, cur.x);
            fma2_step(acc, wbase + (i * 4 + 1) * 128, cur.y);
            fma2_step(acc, wbase + (i * 4 + 2) * 128, cur.z);
            fma2_step(acc, wbase + (i * 4 + 3) * 128, cur.w);
        }

        float* orow = (half ? g_Y : g_Ps) + (size_t)node * OC;
        #pragma unroll
        for (int j = 0; j < 16; j++) {
            float x0, x1, x2, x3;
            asm("mov.b64 {%0, %1}, %2;" : "=f"(x0), "=f"(x1) : "l"(acc[2 * j + 0]));
            asm("mov.b64 {%0, %1}, %2;" : "=f"(x2), "=f"(x3) : "l"(acc[2 * j + 1]));
            reinterpret_cast<float4*>(orow)[j] = make_float4(x0, x1, x2, x3);
        }
    } else {
        // ---- scatter ----
        load_block_offsets(off, t, nsb);
        __syncthreads();

        int e = (blockIdx.x - pblocks) * 256 + t;
        if (e >= n_edges) return;
        int s = __ldg(src + e);
        int d = __ldg(dst + e);
        float4 cs = __ldg(reinterpret_cast<const float4*>(g_featp + (size_t)s * FP));
        float4 cd = __ldg(reinterpret_cast<const float4*>(g_featp + (size_t)d * FP));
        float dx = cs.x - cd.x, dy = cs.y - cd.y, dz = cs.z - cd.z;
        float dd = dx * dx + dy * dy + dz * dz;
        float sc = (dd > 0.f) ? __frcp_rn(dd) : 10000.f;
        int pos = __ldg(g_start + s) + off[s >> 12] + atomicAdd(&g_hist[s], 1);
        g_sorted[pos] = make_int4(d, e, __float_as_int(sc), 0);
    }
}

// ---------------------------------------------------------------------------
// K4: agg + combine fused. Warp per node: edge loop accumulates aggY/bagg/c
// in registers, then directly computes the output row. Re-zeroes g_hist.
// ---------------------------------------------------------------------------
__global__ __launch_bounds__(256) void aggcomb_kernel(
    const float* __restrict__ bond,
    const float* __restrict__ w_n,   // [103][64]
    float* __restrict__ out,
    int n_nodes, int n_edges, int nsb) {

    __shared__ __align__(16) float Wc[25 * OC];   // rows 0..21 Wb, 22..24 Wn[0..2]
    __shared__ int off[32];
    __shared__ float bsh[8][NB];

    int t = threadIdx.x;
    for (int idx = t; idx < 25 * OC; idx += 256) {
        int k = idx >> 6;
        int c = idx & (OC - 1);
        Wc[idx] = (k < NB) ? __ldg(w_n + (NF + k) * OC + c)
                           : __ldg(w_n + (k - NB) * OC + c);
    }
    load_block_offsets(off, t, nsb);
    __syncthreads();

    int wid = t >> 5;
    int lane = t & 31;
    int n = (int)(blockIdx.x * 8 + wid);
    if (n >= n_nodes) return;

    int beg = __ldg(g_start + n) + off[n >> 12];
    int end = (n + 1 < n_nodes) ? (__ldg(g_start + n + 1) + off[(n + 1) >> 12])
                                : n_edges;
    bool hasb = (lane < NB);

    float ay0 = 0.f, ay1 = 0.f, ab = 0.f, ac = 0.f;

    int i = beg;
    for (; i + 3 < end; i += 4) {
        float y0[4], y1[4], bv[4], s[4];
        #pragma unroll
        for (int j = 0; j < 4; j++) {
            int4 r = __ldg(g_sorted + i + j);
            const float* yr = g_Y + (size_t)r.x * OC;
            y0[j] = __ldg(yr + lane);
            y1[j] = __ldg(yr + lane + 32);
            bv[j] = hasb ? __ldg(bond + (size_t)r.y * NB + lane) : 0.f;
            s[j] = __int_as_float(r.z);
        }
        #pragma unroll
        for (int j = 0; j < 4; j++) {
            ay0 += s[j] * y0[j];
            ay1 += s[j] * y1[j];
            ab += bv[j];
            ac += s[j];
        }
    }
    for (; i < end; i++) {
        int4 r = __ldg(g_sorted + i);
        const float* yr = g_Y + (size_t)r.x * OC;
        float y0 = __ldg(yr + lane);
        float y1 = __ldg(yr + lane + 32);
        float bv = hasb ? __ldg(bond + (size_t)r.y * NB + lane) : 0.f;
        float s = __int_as_float(r.z);
        ay0 += s * y0;
        ay1 += s * y1;
        ab += bv;
        ac += s;
    }

    if (lane == 0) g_hist[n] = 0;        // reset cursor for next graph replay

    // exchange bagg within the warp via smem
    if (hasb) bsh[wid][lane] = ab;
    __syncwarp();

    // combine: out = Ps + aggY + c*Y - c*(f0..2 @ Wn[0..2]) + bagg @ Wb
    const float* psr = g_Ps + (size_t)n * OC;
    const float* yr = g_Y + (size_t)n * OC;
    float4 fh = __ldg(reinterpret_cast<const float4*>(g_featp + (size_t)n * FP));
    float cn = ac;

    float r0 = __ldg(psr + lane)      + ay0 + cn * __ldg(yr + lane);
    float r1 = __ldg(psr + lane + 32) + ay1 + cn * __ldg(yr + lane + 32);

    float w0a = Wc[22 * OC + lane], w0b = Wc[22 * OC + lane + 32];
    float w1a = Wc[23 * OC + lane], w1b = Wc[23 * OC + lane + 32];
    float w2a = Wc[24 * OC + lane], w2b = Wc[24 * OC + lane + 32];
    r0 -= cn * (fh.x * w0a + fh.y * w1a + fh.z * w2a);
    r1 -= cn * (fh.x * w0b + fh.y * w1b + fh.z * w2b);

    #pragma unroll
    for (int k = 0; k < NB; k++) {
        float bk = bsh[wid][k];
        r0 += bk * Wc[k * OC + lane];
        r1 += bk * Wc[k * OC + lane + 32];
    }

    out[(size_t)n * OC + lane] = r0;
    out[(size_t)n * OC + lane + 32] = r1;
}

// ---------------------------------------------------------------------------
extern "C" void kernel_launch(void* const* d_in, const int* in_sizes, int n_in,
                              void* d_out, int out_size) {
    const float* feat = (const float*)d_in[0];
    const float* bond = (const float*)d_in[1];
    const float* w_s  = (const float*)d_in[2];
    const float* w_n  = (const float*)d_in[3];
    const int*   src  = (const int*)d_in[4];
    const int*   dst  = (const int*)d_in[5];
    float* out = (float*)d_out;

    int n_nodes = in_sizes[0] / NF;
    int n_edges = in_sizes[4];
    int nsb = (n_nodes + SCAN_B - 1) / SCAN_B;        // 25

    int rblocks = (n_nodes * (FP / 4) + 255) / 256;   // repack
    int hblocks = (n_edges + 255) / 256;              // hist
    int pblocks = (n_nodes + 127) / 128;              // proj
    int sblocks = (n_edges + 255) / 256;              // scatter

    repack_hist_kernel<<<rblocks + hblocks, 256>>>(feat, src, n_nodes, n_edges, rblocks);
    scan1_kernel<<<nsb, SCAN_T>>>(n_nodes);
    scatter_proj_kernel<<<pblocks + sblocks, 256>>>(w_s, w_n, src, dst,
                                                    n_nodes, n_edges, pblocks, nsb);
    aggcomb_kernel<<<(n_nodes + 7) / 8, 256>>>(bond, w_n, out, n_nodes, n_edges, nsb);
}